// round 10
// baseline (speedup 1.0000x reference)
#include <cuda_runtime.h>
#include <cuda_bf16.h>
#include <mma.h>
#include <math.h>
#include <cstdint>

using namespace nvcuda;

// Problem constants (fixed by the dataset)
#define NN 131072        // nodes
#define NE 2097152       // edges

// ---------------------------------------------------------------------------
// Scratch (allocation-free rule: __device__ globals)
// ---------------------------------------------------------------------------
__device__ __align__(16) float g_h0[NN * 16];   // after Linear(16,16)
__device__ __align__(16) float g_h1[NN * 32];   // after block3
__device__ __align__(16) float g_h2[NN * 64];   // after block2
__device__ __align__(16) float g_agg[NN * 64];  // gather output (max C=64)
__device__ __align__(16) float g_rdeg[NN];      // 1/max(deg,1)

__device__ int g_deg[NN];
__device__ int g_rowoff[NN];
__device__ int g_cursor[NN];
__device__ int g_col[NE];
__device__ int g_bsum[512];

// ---------------------------------------------------------------------------
// CSR construction
// ---------------------------------------------------------------------------
__global__ void zero2_int(int* __restrict__ a, int* __restrict__ b) {
    int i = blockIdx.x * blockDim.x + threadIdx.x;
    if (i < NN) { a[i] = 0; b[i] = 0; }
}

__global__ void deg_kernel(const int* __restrict__ dst, int* __restrict__ deg) {
    int e = blockIdx.x * blockDim.x + threadIdx.x;
    if (e < NE) atomicAdd(&deg[dst[e]], 1);
}

// Per-block exclusive scan of 256 elems + block totals + fused rdeg.
__global__ void scanA(const int* __restrict__ deg, int* __restrict__ part,
                      int* __restrict__ bsum, float* __restrict__ rdeg) {
    __shared__ int s[256];
    int t = threadIdx.x;
    int i = blockIdx.x * 256 + t;
    int v = deg[i];
    rdeg[i] = 1.0f / fmaxf((float)v, 1.0f);
    s[t] = v;
    __syncthreads();
    for (int o = 1; o < 256; o <<= 1) {
        int u = (t >= o) ? s[t - o] : 0;
        __syncthreads();
        s[t] += u;
        __syncthreads();
    }
    part[i] = s[t] - v;
    if (t == 255) bsum[blockIdx.x] = s[255];
}

__global__ void scanB(int* __restrict__ bsum) {
    __shared__ int s[512];
    int t = threadIdx.x;
    int v = bsum[t];
    s[t] = v;
    __syncthreads();
    for (int o = 1; o < 512; o <<= 1) {
        int u = (t >= o) ? s[t - o] : 0;
        __syncthreads();
        s[t] += u;
        __syncthreads();
    }
    bsum[t] = s[t] - v;
}

__global__ void scanC(int* __restrict__ part, const int* __restrict__ bsum) {
    int i = blockIdx.x * 256 + threadIdx.x;
    part[i] += bsum[blockIdx.x];
}

__global__ void fill_kernel(const int* __restrict__ src, const int* __restrict__ dst,
                            const int* __restrict__ rowoff, int* __restrict__ cursor,
                            int* __restrict__ col) {
    int e = blockIdx.x * blockDim.x + threadIdx.x;
    if (e >= NE) return;
    int d = dst[e];
    int pos = rowoff[d] + atomicAdd(&cursor[d], 1);
    col[pos] = src[e];
}

// ---------------------------------------------------------------------------
// CSR gather: agg[n] = rdeg[n] * sum_{s in nbrs(n)} h[s]
// One warp per node, (neighbor_slot x C4) float4 lanes, shfl-reduce.
// ---------------------------------------------------------------------------
template <int C4>
__global__ void gather_kernel(const int* __restrict__ rowoff,
                              const int* __restrict__ deg,
                              const int* __restrict__ col,
                              const float* __restrict__ rdeg,
                              const float* __restrict__ h,
                              float* __restrict__ agg) {
    constexpr int SLOTS = 32 / C4;
    int warp = (blockIdx.x * blockDim.x + threadIdx.x) >> 5;
    if (warp >= NN) return;
    int lane = threadIdx.x & 31;
    int slot = lane / C4;
    int c    = lane % C4;

    int start = rowoff[warp];
    int d     = deg[warp];

    const float4* h4 = reinterpret_cast<const float4*>(h);
    float4 acc = make_float4(0.f, 0.f, 0.f, 0.f);

    for (int ni = slot; ni < d; ni += SLOTS) {
        int nbr = col[start + ni];
        float4 v = h4[nbr * C4 + c];
        acc.x += v.x; acc.y += v.y; acc.z += v.z; acc.w += v.w;
    }

#pragma unroll
    for (int off = 16; off >= C4; off >>= 1) {
        acc.x += __shfl_xor_sync(0xFFFFFFFFu, acc.x, off);
        acc.y += __shfl_xor_sync(0xFFFFFFFFu, acc.y, off);
        acc.z += __shfl_xor_sync(0xFFFFFFFFu, acc.z, off);
        acc.w += __shfl_xor_sync(0xFFFFFFFFu, acc.w, off);
    }

    if (lane < C4) {
        float r = rdeg[warp];
        reinterpret_cast<float4*>(agg)[warp * C4 + c] =
            make_float4(acc.x * r, acc.y * r, acc.z * r, acc.w * r);
    }
}

// ---------------------------------------------------------------------------
// Activations
// ---------------------------------------------------------------------------
template <int ACT>
__device__ __forceinline__ float actf(float x) {
    if (ACT == 1) return fmaxf(x, 0.f);
    if (ACT == 2) return 1.0f / (1.0f + __expf(-x));
    return x;
}

// ---------------------------------------------------------------------------
// SIMT fused combine (small layers: linear16, 16->32)
// ---------------------------------------------------------------------------
template <int CIN, int COUT, bool NBR, int ACT>
__global__ void combine_kernel(const float* __restrict__ h,
                               const float* __restrict__ agg,
                               const float* __restrict__ Wself,
                               const float* __restrict__ Wnbr,
                               const float* __restrict__ bias,
                               float* __restrict__ out) {
    constexpr int K  = NBR ? 2 * CIN : CIN;
    constexpr int BN = 64;
    constexpr int TX = COUT / 4;
    constexpr int TY = 256 / TX;
    constexpr int NT = BN / TY;

    extern __shared__ float sm[];
    float* Ws = sm;
    float* Bs = Ws + K * COUT;
    float* Is = Bs + COUT;

    const int tid = threadIdx.x;

    for (int i = tid; i < K * COUT; i += 256) {
        int k = i / COUT, c = i % COUT;
        Ws[i] = (k < CIN) ? Wself[k * COUT + c] : Wnbr[(k - CIN) * COUT + c];
    }
    if (tid < COUT) Bs[tid] = bias[tid];

    const int base = blockIdx.x * BN;

    for (int i = tid; i < BN * K; i += 256) {
        int n = i / K, k = i % K;
        int node = base + n;
        float v;
        if (!NBR || k < CIN) v = h[node * CIN + k];
        else                 v = agg[node * CIN + (k - CIN)];
        Is[n * (K + 1) + k] = v;
    }
    __syncthreads();

    const int tx = tid % TX;
    const int ny = tid / TX;

    float acc[NT][4];
    float4 b4 = *reinterpret_cast<const float4*>(&Bs[tx * 4]);
#pragma unroll
    for (int i = 0; i < NT; i++) {
        acc[i][0] = b4.x; acc[i][1] = b4.y; acc[i][2] = b4.z; acc[i][3] = b4.w;
    }

#pragma unroll 8
    for (int k = 0; k < K; k++) {
        float4 w = *reinterpret_cast<const float4*>(&Ws[k * COUT + tx * 4]);
#pragma unroll
        for (int i = 0; i < NT; i++) {
            float v = Is[(ny * NT + i) * (K + 1) + k];
            acc[i][0] += v * w.x;
            acc[i][1] += v * w.y;
            acc[i][2] += v * w.z;
            acc[i][3] += v * w.w;
        }
    }

#pragma unroll
    for (int i = 0; i < NT; i++) {
        int node = base + ny * NT + i;
        float4 o;
        o.x = actf<ACT>(acc[i][0]);
        o.y = actf<ACT>(acc[i][1]);
        o.z = actf<ACT>(acc[i][2]);
        o.w = actf<ACT>(acc[i][3]);
        *reinterpret_cast<float4*>(&out[node * COUT + tx * 4]) = o;
    }
}

// ---------------------------------------------------------------------------
// TF32 wmma combine (big layers): out = act([h|agg] @ [Ws;Wn] + b)
// BN = 128 nodes/block, 256 threads (8 warps).
// Warp w: node-pair np = w&3 (2 x 16-row tiles at rows np*32),
//         col-half ch = w>>2 (JT = COUT/32 col tiles each).
// fb fragments reused across the 2 node tiles -> 0.75 frag-loads per MMA.
// Requires COUT <= K (staging-buffer reuse for the epilogue).
// ---------------------------------------------------------------------------
__device__ __forceinline__ float f2tf32(float x) {
    float y;
    asm("cvt.rna.tf32.f32 %0, %1;" : "=f"(y) : "f"(x));
    return y;
}

template <int CIN, int COUT, int ACT>
__global__ void __launch_bounds__(256)
wmma_combine_kernel(const float* __restrict__ h,
                    const float* __restrict__ agg,
                    const float* __restrict__ Wself,
                    const float* __restrict__ Wnbr,
                    const float* __restrict__ bias,
                    float* __restrict__ out) {
    constexpr int K   = 2 * CIN;
    constexpr int BN  = 128;
    constexpr int LDI = K + 4;
    constexpr int LDW = COUT + 4;
    constexpr int JT  = COUT / 32;   // col tiles per warp (4 for 128, 2 for 64)
    static_assert(COUT <= K, "staging reuse requires COUT <= K");

    extern __shared__ float sm[];
    float* Is = sm;                  // [BN][LDI]  inputs (tf32), later outputs
    float* Ws = Is + BN * LDI;       // [K][LDW]   weights (tf32)
    float* Bs = Ws + K * LDW;        // [COUT]

    const int tid = threadIdx.x;

    // Stage combined weight (tf32-rounded)
    for (int i = tid; i < K * COUT; i += 256) {
        int k = i / COUT, c = i % COUT;
        float w = (k < CIN) ? Wself[k * COUT + c] : Wnbr[(k - CIN) * COUT + c];
        Ws[k * LDW + c] = f2tf32(w);
    }
    if (tid < COUT) Bs[tid] = bias[tid];

    const int base = blockIdx.x * BN;

    // Stage inputs [h_row | agg_row] (tf32-rounded), float4 reads
    constexpr int Q = K / 4;
    for (int i = tid; i < BN * Q; i += 256) {
        int n = i / Q, q = i % Q;
        float4 v;
        if (q < CIN / 4) v = reinterpret_cast<const float4*>(h)[(size_t)(base + n) * (CIN / 4) + q];
        else             v = reinterpret_cast<const float4*>(agg)[(size_t)(base + n) * (CIN / 4) + (q - CIN / 4)];
        float* d = &Is[n * LDI + q * 4];
        d[0] = f2tf32(v.x); d[1] = f2tf32(v.y); d[2] = f2tf32(v.z); d[3] = f2tf32(v.w);
    }
    __syncthreads();

    const int warp = tid >> 5;
    const int np   = warp & 3;       // node-pair (rows np*32 .. np*32+31)
    const int ch   = warp >> 2;      // col half

    wmma::fragment<wmma::accumulator, 16, 16, 8, float> fc[2][JT];
#pragma unroll
    for (int t = 0; t < 2; t++)
#pragma unroll
        for (int j = 0; j < JT; j++) wmma::fill_fragment(fc[t][j], 0.0f);

#pragma unroll
    for (int k8 = 0; k8 < K / 8; k8++) {
        wmma::fragment<wmma::matrix_a, 16, 16, 8, wmma::precision::tf32, wmma::row_major> fa[2];
#pragma unroll
        for (int t = 0; t < 2; t++)
            wmma::load_matrix_sync(fa[t], &Is[(np * 32 + t * 16) * LDI + k8 * 8], LDI);
#pragma unroll
        for (int j = 0; j < JT; j++) {
            wmma::fragment<wmma::matrix_b, 16, 16, 8, wmma::precision::tf32, wmma::row_major> fb;
            wmma::load_matrix_sync(fb, &Ws[k8 * 8 * LDW + (ch * JT + j) * 16], LDW);
            wmma::mma_sync(fc[0][j], fa[0], fb, fc[0][j]);
            wmma::mma_sync(fc[1][j], fa[1], fb, fc[1][j]);
        }
    }
    __syncthreads();   // all warps done reading Is/Ws

    // Stash accumulators into Is (reused as [BN][LDI] output staging)
#pragma unroll
    for (int t = 0; t < 2; t++)
#pragma unroll
        for (int j = 0; j < JT; j++)
            wmma::store_matrix_sync(&Is[(np * 32 + t * 16) * LDI + (ch * JT + j) * 16],
                                    fc[t][j], LDI, wmma::mem_row_major);
    __syncthreads();

    // Epilogue: bias + activation + coalesced store
    for (int i = tid; i < BN * COUT / 4; i += 256) {
        int n = i / (COUT / 4), q = i % (COUT / 4);
        float4 v = *reinterpret_cast<float4*>(&Is[n * LDI + q * 4]);
        float4 b4 = *reinterpret_cast<const float4*>(&Bs[q * 4]);
        float4 o;
        o.x = actf<ACT>(v.x + b4.x);
        o.y = actf<ACT>(v.y + b4.y);
        o.z = actf<ACT>(v.z + b4.z);
        o.w = actf<ACT>(v.w + b4.w);
        reinterpret_cast<float4*>(out)[(size_t)(base + n) * (COUT / 4) + q] = o;
    }
}

// ---------------------------------------------------------------------------
// Launch
// ---------------------------------------------------------------------------
static inline int smem_bytes(int K, int COUT) {
    return (K * COUT + COUT + 64 * (K + 1)) * (int)sizeof(float);
}
static inline int wmma_smem_bytes(int K, int COUT) {
    return (128 * (K + 4) + K * (COUT + 4) + COUT) * (int)sizeof(float);
}

extern "C" void kernel_launch(void* const* d_in, const int* in_sizes, int n_in,
                              void* d_out, int out_size) {
    const float* x     = (const float*)d_in[0];
    const int*   ei    = (const int*)d_in[1];      // [2, E]
    const float* W_lin = (const float*)d_in[3];
    const float* b_lin = (const float*)d_in[4];
    const float* Ws3   = (const float*)d_in[5];
    const float* Wn3   = (const float*)d_in[6];
    const float* b3    = (const float*)d_in[7];
    const float* Ws2   = (const float*)d_in[8];
    const float* Wn2   = (const float*)d_in[9];
    const float* b2    = (const float*)d_in[10];
    const float* Ws1   = (const float*)d_in[11];
    const float* Wn1   = (const float*)d_in[12];
    const float* b1    = (const float*)d_in[13];
    float* out = (float*)d_out;

    const int* src = ei;
    const int* dst = ei + NE;

    float *h0, *h1, *h2, *agg, *rdeg;
    int *deg, *rowoff, *cursor, *col, *bsum;
    cudaGetSymbolAddress((void**)&h0,     g_h0);
    cudaGetSymbolAddress((void**)&h1,     g_h1);
    cudaGetSymbolAddress((void**)&h2,     g_h2);
    cudaGetSymbolAddress((void**)&agg,    g_agg);
    cudaGetSymbolAddress((void**)&rdeg,   g_rdeg);
    cudaGetSymbolAddress((void**)&deg,    g_deg);
    cudaGetSymbolAddress((void**)&rowoff, g_rowoff);
    cudaGetSymbolAddress((void**)&cursor, g_cursor);
    cudaGetSymbolAddress((void**)&col,    g_col);
    cudaGetSymbolAddress((void**)&bsum,   g_bsum);

    const int wsmem_L1 = wmma_smem_bytes(128, 128);   // ~136KB
    const int wsmem_L2 = wmma_smem_bytes(64, 64);     // ~52KB
    cudaFuncSetAttribute((const void*)wmma_combine_kernel<64, 128, 2>,
                         cudaFuncAttributeMaxDynamicSharedMemorySize, wsmem_L1 + 1024);
    cudaFuncSetAttribute((const void*)wmma_combine_kernel<32, 64, 1>,
                         cudaFuncAttributeMaxDynamicSharedMemorySize, wsmem_L2 + 1024);

    const int T  = 256;
    const int NB = NN / 64;          // SIMT combine grid
    const int WB = NN / 128;         // wmma combine grid
    const int GW = NN * 32 / T;      // gather grid (1 warp/node)

    // ---- CSR build ----
    zero2_int<<<NN / T, T>>>(deg, cursor);
    deg_kernel<<<NE / T, T>>>(dst, deg);
    scanA<<<512, 256>>>(deg, rowoff, bsum, rdeg);
    scanB<<<1, 512>>>(bsum);
    scanC<<<512, 256>>>(rowoff, bsum);
    fill_kernel<<<NE / T, T>>>(src, dst, rowoff, cursor, col);

    // ---- Linear(16,16) ----
    combine_kernel<16, 16, false, 0><<<NB, T, smem_bytes(16, 16)>>>(
        x, nullptr, W_lin, nullptr, b_lin, h0);

    // ---- Block3: 16 -> 32, relu (SIMT) ----
    gather_kernel<4><<<GW, T>>>(rowoff, deg, col, rdeg, h0, agg);
    combine_kernel<16, 32, true, 1><<<NB, T, smem_bytes(32, 32)>>>(
        h0, agg, Ws3, Wn3, b3, h1);

    // ---- Block2: 32 -> 64, relu (wmma tf32) ----
    gather_kernel<8><<<GW, T>>>(rowoff, deg, col, rdeg, h1, agg);
    wmma_combine_kernel<32, 64, 1><<<WB, T, wsmem_L2>>>(
        h1, agg, Ws2, Wn2, b2, h2);

    // ---- Block1: 64 -> 128, sigmoid -> d_out (wmma tf32) ----
    gather_kernel<16><<<GW, T>>>(rowoff, deg, col, rdeg, h2, agg);
    wmma_combine_kernel<64, 128, 2><<<WB, T, wsmem_L1>>>(
        h2, agg, Ws1, Wn1, b1, out);
}

// round 11
// speedup vs baseline: 1.1196x; 1.1196x over previous
#include <cuda_runtime.h>
#include <cuda_bf16.h>
#include <mma.h>
#include <math.h>
#include <cstdint>

using namespace nvcuda;

// Problem constants (fixed by the dataset)
#define NN 131072        // nodes
#define NE 2097152       // edges

// ---------------------------------------------------------------------------
// Scratch (allocation-free rule: __device__ globals)
// ---------------------------------------------------------------------------
__device__ __align__(16) float g_h0[NN * 16];   // after Linear(16,16)
__device__ __align__(16) float g_h1[NN * 32];   // after block3
__device__ __align__(16) float g_h2[NN * 64];   // after block2
__device__ __align__(16) float g_agg[NN * 64];  // gather output (max C=64)
__device__ __align__(16) float g_rdeg[NN];      // 1/max(deg,1)

__device__ __align__(16) float g_W1t[128 * 128];  // combined [Ws1;Wn1], tf32
__device__ __align__(16) float g_W2t[64 * 64];    // combined [Ws2;Wn2], tf32

__device__ int g_deg[NN];
__device__ int g_rowoff[NN];
__device__ int g_cursor[NN];
__device__ int g_col[NE];
__device__ int g_bsum[512];

// ---------------------------------------------------------------------------
// CSR construction
// ---------------------------------------------------------------------------
__global__ void zero2_int(int* __restrict__ a, int* __restrict__ b) {
    int i = blockIdx.x * blockDim.x + threadIdx.x;
    if (i < NN) { a[i] = 0; b[i] = 0; }
}

__global__ void deg_kernel(const int* __restrict__ dst, int* __restrict__ deg) {
    int e = blockIdx.x * blockDim.x + threadIdx.x;
    if (e < NE) atomicAdd(&deg[dst[e]], 1);
}

// Per-block exclusive scan of 256 elems + block totals + fused rdeg.
__global__ void scanA(const int* __restrict__ deg, int* __restrict__ part,
                      int* __restrict__ bsum, float* __restrict__ rdeg) {
    __shared__ int s[256];
    int t = threadIdx.x;
    int i = blockIdx.x * 256 + t;
    int v = deg[i];
    rdeg[i] = 1.0f / fmaxf((float)v, 1.0f);
    s[t] = v;
    __syncthreads();
    for (int o = 1; o < 256; o <<= 1) {
        int u = (t >= o) ? s[t - o] : 0;
        __syncthreads();
        s[t] += u;
        __syncthreads();
    }
    part[i] = s[t] - v;
    if (t == 255) bsum[blockIdx.x] = s[255];
}

__global__ void scanB(int* __restrict__ bsum) {
    __shared__ int s[512];
    int t = threadIdx.x;
    int v = bsum[t];
    s[t] = v;
    __syncthreads();
    for (int o = 1; o < 512; o <<= 1) {
        int u = (t >= o) ? s[t - o] : 0;
        __syncthreads();
        s[t] += u;
        __syncthreads();
    }
    bsum[t] = s[t] - v;
}

__global__ void scanC(int* __restrict__ part, const int* __restrict__ bsum) {
    int i = blockIdx.x * 256 + threadIdx.x;
    part[i] += bsum[blockIdx.x];
}

__global__ void fill_kernel(const int* __restrict__ src, const int* __restrict__ dst,
                            const int* __restrict__ rowoff, int* __restrict__ cursor,
                            int* __restrict__ col) {
    int e = blockIdx.x * blockDim.x + threadIdx.x;
    if (e >= NE) return;
    int d = dst[e];
    int pos = rowoff[d] + atomicAdd(&cursor[d], 1);
    col[pos] = src[e];
}

// ---------------------------------------------------------------------------
// Weight prep: combined [Wself;Wnbr] -> tf32, once per launch (global buffer)
// ---------------------------------------------------------------------------
__device__ __forceinline__ float f2tf32(float x) {
    float y;
    asm("cvt.rna.tf32.f32 %0, %1;" : "=f"(y) : "f"(x));
    return y;
}

__global__ void prep_w(const float* __restrict__ Ws1, const float* __restrict__ Wn1,
                       const float* __restrict__ Ws2, const float* __restrict__ Wn2) {
    int i = blockIdx.x * blockDim.x + threadIdx.x;
    if (i < 128 * 128) {
        int k = i >> 7, c = i & 127;
        float w = (k < 64) ? Ws1[k * 128 + c] : Wn1[(k - 64) * 128 + c];
        g_W1t[i] = f2tf32(w);
    }
    if (i < 64 * 64) {
        int k = i >> 6, c = i & 63;
        float w = (k < 32) ? Ws2[k * 64 + c] : Wn2[(k - 32) * 64 + c];
        g_W2t[i] = f2tf32(w);
    }
}

// ---------------------------------------------------------------------------
// CSR gather: agg[n] = rdeg[n] * sum_{s in nbrs(n)} h[s]
// One warp per node, (neighbor_slot x C4) float4 lanes, shfl-reduce.
// ---------------------------------------------------------------------------
template <int C4>
__global__ void gather_kernel(const int* __restrict__ rowoff,
                              const int* __restrict__ deg,
                              const int* __restrict__ col,
                              const float* __restrict__ rdeg,
                              const float* __restrict__ h,
                              float* __restrict__ agg) {
    constexpr int SLOTS = 32 / C4;
    int warp = (blockIdx.x * blockDim.x + threadIdx.x) >> 5;
    if (warp >= NN) return;
    int lane = threadIdx.x & 31;
    int slot = lane / C4;
    int c    = lane % C4;

    int start = rowoff[warp];
    int d     = deg[warp];

    const float4* h4 = reinterpret_cast<const float4*>(h);
    float4 acc = make_float4(0.f, 0.f, 0.f, 0.f);

    for (int ni = slot; ni < d; ni += SLOTS) {
        int nbr = col[start + ni];
        float4 v = h4[nbr * C4 + c];
        acc.x += v.x; acc.y += v.y; acc.z += v.z; acc.w += v.w;
    }

#pragma unroll
    for (int off = 16; off >= C4; off >>= 1) {
        acc.x += __shfl_xor_sync(0xFFFFFFFFu, acc.x, off);
        acc.y += __shfl_xor_sync(0xFFFFFFFFu, acc.y, off);
        acc.z += __shfl_xor_sync(0xFFFFFFFFu, acc.z, off);
        acc.w += __shfl_xor_sync(0xFFFFFFFFu, acc.w, off);
    }

    if (lane < C4) {
        float r = rdeg[warp];
        reinterpret_cast<float4*>(agg)[warp * C4 + c] =
            make_float4(acc.x * r, acc.y * r, acc.z * r, acc.w * r);
    }
}

// ---------------------------------------------------------------------------
// Activations
// ---------------------------------------------------------------------------
template <int ACT>
__device__ __forceinline__ float actf(float x) {
    if (ACT == 1) return fmaxf(x, 0.f);
    if (ACT == 2) return 1.0f / (1.0f + __expf(-x));
    return x;
}

// ---------------------------------------------------------------------------
// SIMT fused combine (small layers: linear16, 16->32)
// ---------------------------------------------------------------------------
template <int CIN, int COUT, bool NBR, int ACT>
__global__ void combine_kernel(const float* __restrict__ h,
                               const float* __restrict__ agg,
                               const float* __restrict__ Wself,
                               const float* __restrict__ Wnbr,
                               const float* __restrict__ bias,
                               float* __restrict__ out) {
    constexpr int K  = NBR ? 2 * CIN : CIN;
    constexpr int BN = 64;
    constexpr int TX = COUT / 4;
    constexpr int TY = 256 / TX;
    constexpr int NT = BN / TY;

    extern __shared__ float sm[];
    float* Ws = sm;
    float* Bs = Ws + K * COUT;
    float* Is = Bs + COUT;

    const int tid = threadIdx.x;

    for (int i = tid; i < K * COUT; i += 256) {
        int k = i / COUT, c = i % COUT;
        Ws[i] = (k < CIN) ? Wself[k * COUT + c] : Wnbr[(k - CIN) * COUT + c];
    }
    if (tid < COUT) Bs[tid] = bias[tid];

    const int base = blockIdx.x * BN;

    for (int i = tid; i < BN * K; i += 256) {
        int n = i / K, k = i % K;
        int node = base + n;
        float v;
        if (!NBR || k < CIN) v = h[node * CIN + k];
        else                 v = agg[node * CIN + (k - CIN)];
        Is[n * (K + 1) + k] = v;
    }
    __syncthreads();

    const int tx = tid % TX;
    const int ny = tid / TX;

    float acc[NT][4];
    float4 b4 = *reinterpret_cast<const float4*>(&Bs[tx * 4]);
#pragma unroll
    for (int i = 0; i < NT; i++) {
        acc[i][0] = b4.x; acc[i][1] = b4.y; acc[i][2] = b4.z; acc[i][3] = b4.w;
    }

#pragma unroll 8
    for (int k = 0; k < K; k++) {
        float4 w = *reinterpret_cast<const float4*>(&Ws[k * COUT + tx * 4]);
#pragma unroll
        for (int i = 0; i < NT; i++) {
            float v = Is[(ny * NT + i) * (K + 1) + k];
            acc[i][0] += v * w.x;
            acc[i][1] += v * w.y;
            acc[i][2] += v * w.z;
            acc[i][3] += v * w.w;
        }
    }

#pragma unroll
    for (int i = 0; i < NT; i++) {
        int node = base + ny * NT + i;
        float4 o;
        o.x = actf<ACT>(acc[i][0]);
        o.y = actf<ACT>(acc[i][1]);
        o.z = actf<ACT>(acc[i][2]);
        o.w = actf<ACT>(acc[i][3]);
        *reinterpret_cast<float4*>(&out[node * COUT + tx * 4]) = o;
    }
}

// ---------------------------------------------------------------------------
// TF32 wmma combine v2: out = act([h|agg] @ Wt + b)
// Wt = precomputed combined tf32 weights in GLOBAL memory (L1/L2-resident);
// fb fragments load straight from global -> no weight staging, small smem.
// BN = 128 nodes/block, 256 threads (8 warps).
// Warp w: node-pair np = w&3 (2 x 16-row tiles), col-half ch = w>>2.
// smem = input tile only: L1 68KB (2 CTA/SM), L2 35KB (4 CTA/SM).
// Requires COUT <= K (epilogue staging reuse).
// ---------------------------------------------------------------------------
template <int CIN, int COUT, int ACT>
__global__ void __launch_bounds__(256)
wmma_combine_kernel(const float* __restrict__ h,
                    const float* __restrict__ agg,
                    const float* __restrict__ Wt,
                    const float* __restrict__ bias,
                    float* __restrict__ out) {
    constexpr int K   = 2 * CIN;
    constexpr int BN  = 128;
    constexpr int LDI = K + 4;
    constexpr int JT  = COUT / 32;   // col tiles per warp (4 for 128, 2 for 64)
    static_assert(COUT <= K, "staging reuse requires COUT <= K");

    extern __shared__ float sm[];
    float* Is = sm;                  // [BN][LDI]  inputs (tf32), later outputs
    float* Bs = Is + BN * LDI;       // [COUT]

    const int tid  = threadIdx.x;
    const int base = blockIdx.x * BN;

    if (tid < COUT) Bs[tid] = bias[tid];

    // Stage inputs [h_row | agg_row] (tf32-rounded), float4 reads
    constexpr int Q = K / 4;
    for (int i = tid; i < BN * Q; i += 256) {
        int n = i / Q, q = i % Q;
        float4 v;
        if (q < CIN / 4) v = reinterpret_cast<const float4*>(h)[(size_t)(base + n) * (CIN / 4) + q];
        else             v = reinterpret_cast<const float4*>(agg)[(size_t)(base + n) * (CIN / 4) + (q - CIN / 4)];
        float* d = &Is[n * LDI + q * 4];
        d[0] = f2tf32(v.x); d[1] = f2tf32(v.y); d[2] = f2tf32(v.z); d[3] = f2tf32(v.w);
    }
    __syncthreads();

    const int warp = tid >> 5;
    const int np   = warp & 3;       // node-pair (rows np*32 .. np*32+31)
    const int ch   = warp >> 2;      // col half

    wmma::fragment<wmma::accumulator, 16, 16, 8, float> fc[2][JT];
#pragma unroll
    for (int t = 0; t < 2; t++)
#pragma unroll
        for (int j = 0; j < JT; j++) wmma::fill_fragment(fc[t][j], 0.0f);

#pragma unroll
    for (int k8 = 0; k8 < K / 8; k8++) {
        wmma::fragment<wmma::matrix_a, 16, 16, 8, wmma::precision::tf32, wmma::row_major> fa[2];
#pragma unroll
        for (int t = 0; t < 2; t++)
            wmma::load_matrix_sync(fa[t], &Is[(np * 32 + t * 16) * LDI + k8 * 8], LDI);
#pragma unroll
        for (int j = 0; j < JT; j++) {
            wmma::fragment<wmma::matrix_b, 16, 16, 8, wmma::precision::tf32, wmma::row_major> fb;
            wmma::load_matrix_sync(fb, &Wt[k8 * 8 * COUT + (ch * JT + j) * 16], COUT);
            wmma::mma_sync(fc[0][j], fa[0], fb, fc[0][j]);
            wmma::mma_sync(fc[1][j], fa[1], fb, fc[1][j]);
        }
    }
    __syncthreads();   // all warps done reading Is

    // Stash accumulators into Is (reused as [BN][LDI] output staging)
#pragma unroll
    for (int t = 0; t < 2; t++)
#pragma unroll
        for (int j = 0; j < JT; j++)
            wmma::store_matrix_sync(&Is[(np * 32 + t * 16) * LDI + (ch * JT + j) * 16],
                                    fc[t][j], LDI, wmma::mem_row_major);
    __syncthreads();

    // Epilogue: bias + activation + coalesced store
    for (int i = tid; i < BN * COUT / 4; i += 256) {
        int n = i / (COUT / 4), q = i % (COUT / 4);
        float4 v = *reinterpret_cast<float4*>(&Is[n * LDI + q * 4]);
        float4 b4 = *reinterpret_cast<const float4*>(&Bs[q * 4]);
        float4 o;
        o.x = actf<ACT>(v.x + b4.x);
        o.y = actf<ACT>(v.y + b4.y);
        o.z = actf<ACT>(v.z + b4.z);
        o.w = actf<ACT>(v.w + b4.w);
        reinterpret_cast<float4*>(out)[(size_t)(base + n) * (COUT / 4) + q] = o;
    }
}

// ---------------------------------------------------------------------------
// Launch
// ---------------------------------------------------------------------------
static inline int smem_bytes(int K, int COUT) {
    return (K * COUT + COUT + 64 * (K + 1)) * (int)sizeof(float);
}
static inline int wmma_smem_bytes(int K, int COUT) {
    return (128 * (K + 4) + COUT) * (int)sizeof(float);
}

extern "C" void kernel_launch(void* const* d_in, const int* in_sizes, int n_in,
                              void* d_out, int out_size) {
    const float* x     = (const float*)d_in[0];
    const int*   ei    = (const int*)d_in[1];      // [2, E]
    const float* W_lin = (const float*)d_in[3];
    const float* b_lin = (const float*)d_in[4];
    const float* Ws3   = (const float*)d_in[5];
    const float* Wn3   = (const float*)d_in[6];
    const float* b3    = (const float*)d_in[7];
    const float* Ws2   = (const float*)d_in[8];
    const float* Wn2   = (const float*)d_in[9];
    const float* b2    = (const float*)d_in[10];
    const float* Ws1   = (const float*)d_in[11];
    const float* Wn1   = (const float*)d_in[12];
    const float* b1    = (const float*)d_in[13];
    float* out = (float*)d_out;

    const int* src = ei;
    const int* dst = ei + NE;

    float *h0, *h1, *h2, *agg, *rdeg, *W1t, *W2t;
    int *deg, *rowoff, *cursor, *col, *bsum;
    cudaGetSymbolAddress((void**)&h0,     g_h0);
    cudaGetSymbolAddress((void**)&h1,     g_h1);
    cudaGetSymbolAddress((void**)&h2,     g_h2);
    cudaGetSymbolAddress((void**)&agg,    g_agg);
    cudaGetSymbolAddress((void**)&rdeg,   g_rdeg);
    cudaGetSymbolAddress((void**)&W1t,    g_W1t);
    cudaGetSymbolAddress((void**)&W2t,    g_W2t);
    cudaGetSymbolAddress((void**)&deg,    g_deg);
    cudaGetSymbolAddress((void**)&rowoff, g_rowoff);
    cudaGetSymbolAddress((void**)&cursor, g_cursor);
    cudaGetSymbolAddress((void**)&col,    g_col);
    cudaGetSymbolAddress((void**)&bsum,   g_bsum);

    const int wsmem_L1 = wmma_smem_bytes(128, 128);   // ~68KB
    const int wsmem_L2 = wmma_smem_bytes(64, 64);     // ~35KB
    cudaFuncSetAttribute((const void*)wmma_combine_kernel<64, 128, 2>,
                         cudaFuncAttributeMaxDynamicSharedMemorySize, wsmem_L1 + 1024);
    cudaFuncSetAttribute((const void*)wmma_combine_kernel<32, 64, 1>,
                         cudaFuncAttributeMaxDynamicSharedMemorySize, wsmem_L2 + 1024);

    const int T  = 256;
    const int NB = NN / 64;          // SIMT combine grid
    const int WB = NN / 128;         // wmma combine grid
    const int GW = NN * 32 / T;      // gather grid (1 warp/node)

    // ---- CSR build + weight prep ----
    zero2_int<<<NN / T, T>>>(deg, cursor);
    deg_kernel<<<NE / T, T>>>(dst, deg);
    scanA<<<512, 256>>>(deg, rowoff, bsum, rdeg);
    scanB<<<1, 512>>>(bsum);
    scanC<<<512, 256>>>(rowoff, bsum);
    fill_kernel<<<NE / T, T>>>(src, dst, rowoff, cursor, col);
    prep_w<<<64, 256>>>(Ws1, Wn1, Ws2, Wn2);

    // ---- Linear(16,16) ----
    combine_kernel<16, 16, false, 0><<<NB, T, smem_bytes(16, 16)>>>(
        x, nullptr, W_lin, nullptr, b_lin, h0);

    // ---- Block3: 16 -> 32, relu (SIMT) ----
    gather_kernel<4><<<GW, T>>>(rowoff, deg, col, rdeg, h0, agg);
    combine_kernel<16, 32, true, 1><<<NB, T, smem_bytes(32, 32)>>>(
        h0, agg, Ws3, Wn3, b3, h1);

    // ---- Block2: 32 -> 64, relu (wmma tf32, weights from global) ----
    gather_kernel<8><<<GW, T>>>(rowoff, deg, col, rdeg, h1, agg);
    wmma_combine_kernel<32, 64, 1><<<WB, T, wsmem_L2>>>(
        h1, agg, W2t, b2, h2);

    // ---- Block1: 64 -> 128, sigmoid -> d_out (wmma tf32) ----
    gather_kernel<16><<<GW, T>>>(rowoff, deg, col, rdeg, h2, agg);
    wmma_combine_kernel<64, 128, 2><<<WB, T, wsmem_L1>>>(
        h2, agg, W1t, b1, out);
}

// round 12
// speedup vs baseline: 1.1538x; 1.0305x over previous
#include <cuda_runtime.h>
#include <cuda_bf16.h>
#include <mma.h>
#include <math.h>
#include <cstdint>

using namespace nvcuda;

// Problem constants (fixed by the dataset)
#define NN 131072        // nodes
#define NE 2097152       // edges

// ---------------------------------------------------------------------------
// Scratch (allocation-free rule: __device__ globals)
// ---------------------------------------------------------------------------
__device__ __align__(16) float g_h0[NN * 16];   // after Linear(16,16)
__device__ __align__(16) float g_h1[NN * 32];   // after block3
__device__ __align__(16) float g_h2[NN * 64];   // after block2
__device__ __align__(16) float g_agg[NN * 16];  // gather output (layer3 only)
__device__ __align__(16) float g_rdeg[NN];      // 1/max(deg,1)

__device__ __align__(16) float g_W1t[128 * 128];  // combined [Ws1;Wn1], tf32
__device__ __align__(16) float g_W2t[64 * 64];    // combined [Ws2;Wn2], tf32

__device__ int g_deg[NN];
__device__ int g_rowoff[NN];
__device__ int g_cursor[NN];
__device__ int g_col[NE];
__device__ int g_bsum[512];

// ---------------------------------------------------------------------------
// CSR construction
// ---------------------------------------------------------------------------
__global__ void zero2_int(int* __restrict__ a, int* __restrict__ b) {
    int i = blockIdx.x * blockDim.x + threadIdx.x;
    if (i < NN) { a[i] = 0; b[i] = 0; }
}

__global__ void deg_kernel(const int* __restrict__ dst, int* __restrict__ deg) {
    int e = blockIdx.x * blockDim.x + threadIdx.x;
    if (e < NE) atomicAdd(&deg[dst[e]], 1);
}

// Per-block exclusive scan of 256 elems + block totals + fused rdeg.
__global__ void scanA(const int* __restrict__ deg, int* __restrict__ part,
                      int* __restrict__ bsum, float* __restrict__ rdeg) {
    __shared__ int s[256];
    int t = threadIdx.x;
    int i = blockIdx.x * 256 + t;
    int v = deg[i];
    rdeg[i] = 1.0f / fmaxf((float)v, 1.0f);
    s[t] = v;
    __syncthreads();
    for (int o = 1; o < 256; o <<= 1) {
        int u = (t >= o) ? s[t - o] : 0;
        __syncthreads();
        s[t] += u;
        __syncthreads();
    }
    part[i] = s[t] - v;
    if (t == 255) bsum[blockIdx.x] = s[255];
}

__global__ void scanB(int* __restrict__ bsum) {
    __shared__ int s[512];
    int t = threadIdx.x;
    int v = bsum[t];
    s[t] = v;
    __syncthreads();
    for (int o = 1; o < 512; o <<= 1) {
        int u = (t >= o) ? s[t - o] : 0;
        __syncthreads();
        s[t] += u;
        __syncthreads();
    }
    bsum[t] = s[t] - v;
}

__global__ void scanC(int* __restrict__ part, const int* __restrict__ bsum) {
    int i = blockIdx.x * 256 + threadIdx.x;
    part[i] += bsum[blockIdx.x];
}

__global__ void fill_kernel(const int* __restrict__ src, const int* __restrict__ dst,
                            const int* __restrict__ rowoff, int* __restrict__ cursor,
                            int* __restrict__ col) {
    int e = blockIdx.x * blockDim.x + threadIdx.x;
    if (e >= NE) return;
    int d = dst[e];
    int pos = rowoff[d] + atomicAdd(&cursor[d], 1);
    col[pos] = src[e];
}

// ---------------------------------------------------------------------------
// Weight prep: combined [Wself;Wnbr] -> tf32, once per launch (global buffer)
// ---------------------------------------------------------------------------
__device__ __forceinline__ float f2tf32(float x) {
    float y;
    asm("cvt.rna.tf32.f32 %0, %1;" : "=f"(y) : "f"(x));
    return y;
}

__global__ void prep_w(const float* __restrict__ Ws1, const float* __restrict__ Wn1,
                       const float* __restrict__ Ws2, const float* __restrict__ Wn2) {
    int i = blockIdx.x * blockDim.x + threadIdx.x;
    if (i < 128 * 128) {
        int k = i >> 7, c = i & 127;
        float w = (k < 64) ? Ws1[k * 128 + c] : Wn1[(k - 64) * 128 + c];
        g_W1t[i] = f2tf32(w);
    }
    if (i < 64 * 64) {
        int k = i >> 6, c = i & 63;
        float w = (k < 32) ? Ws2[k * 64 + c] : Wn2[(k - 32) * 64 + c];
        g_W2t[i] = f2tf32(w);
    }
}

// ---------------------------------------------------------------------------
// Standalone CSR gather (layer3 only, C=16): agg[n] = rdeg[n]*sum h[nbr]
// ---------------------------------------------------------------------------
template <int C4>
__global__ void gather_kernel(const int* __restrict__ rowoff,
                              const int* __restrict__ deg,
                              const int* __restrict__ col,
                              const float* __restrict__ rdeg,
                              const float* __restrict__ h,
                              float* __restrict__ agg) {
    constexpr int SLOTS = 32 / C4;
    int warp = (blockIdx.x * blockDim.x + threadIdx.x) >> 5;
    if (warp >= NN) return;
    int lane = threadIdx.x & 31;
    int slot = lane / C4;
    int c    = lane % C4;

    int start = rowoff[warp];
    int d     = deg[warp];

    const float4* h4 = reinterpret_cast<const float4*>(h);
    float4 acc = make_float4(0.f, 0.f, 0.f, 0.f);

    for (int ni = slot; ni < d; ni += SLOTS) {
        int nbr = col[start + ni];
        float4 v = h4[nbr * C4 + c];
        acc.x += v.x; acc.y += v.y; acc.z += v.z; acc.w += v.w;
    }

#pragma unroll
    for (int off = 16; off >= C4; off >>= 1) {
        acc.x += __shfl_xor_sync(0xFFFFFFFFu, acc.x, off);
        acc.y += __shfl_xor_sync(0xFFFFFFFFu, acc.y, off);
        acc.z += __shfl_xor_sync(0xFFFFFFFFu, acc.z, off);
        acc.w += __shfl_xor_sync(0xFFFFFFFFu, acc.w, off);
    }

    if (lane < C4) {
        float r = rdeg[warp];
        reinterpret_cast<float4*>(agg)[warp * C4 + c] =
            make_float4(acc.x * r, acc.y * r, acc.z * r, acc.w * r);
    }
}

// ---------------------------------------------------------------------------
// Activations
// ---------------------------------------------------------------------------
template <int ACT>
__device__ __forceinline__ float actf(float x) {
    if (ACT == 1) return fmaxf(x, 0.f);
    if (ACT == 2) return 1.0f / (1.0f + __expf(-x));
    return x;
}

// ---------------------------------------------------------------------------
// SIMT fused combine (small layers: linear16, 16->32)
// ---------------------------------------------------------------------------
template <int CIN, int COUT, bool NBR, int ACT>
__global__ void combine_kernel(const float* __restrict__ h,
                               const float* __restrict__ agg,
                               const float* __restrict__ Wself,
                               const float* __restrict__ Wnbr,
                               const float* __restrict__ bias,
                               float* __restrict__ out) {
    constexpr int K  = NBR ? 2 * CIN : CIN;
    constexpr int BN = 64;
    constexpr int TX = COUT / 4;
    constexpr int TY = 256 / TX;
    constexpr int NT = BN / TY;

    extern __shared__ float sm[];
    float* Ws = sm;
    float* Bs = Ws + K * COUT;
    float* Is = Bs + COUT;

    const int tid = threadIdx.x;

    for (int i = tid; i < K * COUT; i += 256) {
        int k = i / COUT, c = i % COUT;
        Ws[i] = (k < CIN) ? Wself[k * COUT + c] : Wnbr[(k - CIN) * COUT + c];
    }
    if (tid < COUT) Bs[tid] = bias[tid];

    const int base = blockIdx.x * BN;

    for (int i = tid; i < BN * K; i += 256) {
        int n = i / K, k = i % K;
        int node = base + n;
        float v;
        if (!NBR || k < CIN) v = h[node * CIN + k];
        else                 v = agg[node * CIN + (k - CIN)];
        Is[n * (K + 1) + k] = v;
    }
    __syncthreads();

    const int tx = tid % TX;
    const int ny = tid / TX;

    float acc[NT][4];
    float4 b4 = *reinterpret_cast<const float4*>(&Bs[tx * 4]);
#pragma unroll
    for (int i = 0; i < NT; i++) {
        acc[i][0] = b4.x; acc[i][1] = b4.y; acc[i][2] = b4.z; acc[i][3] = b4.w;
    }

#pragma unroll 8
    for (int k = 0; k < K; k++) {
        float4 w = *reinterpret_cast<const float4*>(&Ws[k * COUT + tx * 4]);
#pragma unroll
        for (int i = 0; i < NT; i++) {
            float v = Is[(ny * NT + i) * (K + 1) + k];
            acc[i][0] += v * w.x;
            acc[i][1] += v * w.y;
            acc[i][2] += v * w.z;
            acc[i][3] += v * w.w;
        }
    }

#pragma unroll
    for (int i = 0; i < NT; i++) {
        int node = base + ny * NT + i;
        float4 o;
        o.x = actf<ACT>(acc[i][0]);
        o.y = actf<ACT>(acc[i][1]);
        o.z = actf<ACT>(acc[i][2]);
        o.w = actf<ACT>(acc[i][3]);
        *reinterpret_cast<float4*>(&out[node * COUT + tx * 4]) = o;
    }
}

// ---------------------------------------------------------------------------
// Fused gather + TF32 wmma combine (big layers):
//   out = act([h | rdeg*sum_nbr h] @ Wt + b)
// 512 threads (16 warps), BN = 128 nodes/block.
// Phase 1: stage self rows (tf32) + in-block CSR gather into smem (tf32).
// Phase 2: wmma; warp w: node-tile nt=w&7 (16 rows), col-half ch=w>>3,
//          JT=COUT/32 col tiles. fb fragments straight from global Wt.
// Requires COUT <= K (epilogue staging reuse).
// ---------------------------------------------------------------------------
template <int CIN, int COUT, int ACT>
__global__ void __launch_bounds__(512)
wmma_fused_kernel(const float* __restrict__ h,
                  const int* __restrict__ rowoff,
                  const int* __restrict__ deg,
                  const int* __restrict__ col,
                  const float* __restrict__ rdeg,
                  const float* __restrict__ Wt,
                  const float* __restrict__ bias,
                  float* __restrict__ out) {
    constexpr int K   = 2 * CIN;
    constexpr int BN  = 128;
    constexpr int LDI = K + 4;
    constexpr int JT  = COUT / 32;
    constexpr int C4  = CIN / 4;     // float4 chunks per input row
    constexpr int SLOTS = 32 / C4;
    static_assert(COUT <= K, "staging reuse requires COUT <= K");

    extern __shared__ float sm[];
    float* Is = sm;                  // [BN][LDI]  inputs (tf32), later outputs
    float* Bs = Is + BN * LDI;       // [COUT]

    const int tid  = threadIdx.x;
    const int base = blockIdx.x * BN;

    if (tid < COUT) Bs[tid] = bias[tid];

    // ---- Phase 1a: stage self rows (tf32) ----
    for (int i = tid; i < BN * C4; i += 512) {
        int n = i / C4, q = i % C4;
        float4 v = reinterpret_cast<const float4*>(h)[(size_t)(base + n) * C4 + q];
        float* d = &Is[n * LDI + q * 4];
        d[0] = f2tf32(v.x); d[1] = f2tf32(v.y); d[2] = f2tf32(v.z); d[3] = f2tf32(v.w);
    }

    // ---- Phase 1b: in-block gather -> Is[n][CIN..K) ----
    {
        const int warp = tid >> 5;
        const int lane = tid & 31;
        const int slot = lane / C4;
        const int c    = lane % C4;
        const float4* h4 = reinterpret_cast<const float4*>(h);

#pragma unroll
        for (int j = 0; j < BN / 16; j++) {      // 8 nodes per warp
            int nloc = warp * (BN / 16) + j;
            int node = base + nloc;
            int st = rowoff[node];
            int d  = deg[node];
            float4 acc = make_float4(0.f, 0.f, 0.f, 0.f);
            for (int ni = slot; ni < d; ni += SLOTS) {
                int nbr = col[st + ni];
                float4 v = h4[(size_t)nbr * C4 + c];
                acc.x += v.x; acc.y += v.y; acc.z += v.z; acc.w += v.w;
            }
#pragma unroll
            for (int off = 16; off >= C4; off >>= 1) {
                acc.x += __shfl_xor_sync(0xFFFFFFFFu, acc.x, off);
                acc.y += __shfl_xor_sync(0xFFFFFFFFu, acc.y, off);
                acc.z += __shfl_xor_sync(0xFFFFFFFFu, acc.z, off);
                acc.w += __shfl_xor_sync(0xFFFFFFFFu, acc.w, off);
            }
            if (lane < C4) {
                float r = rdeg[node];
                float* dptr = &Is[nloc * LDI + CIN + c * 4];
                dptr[0] = f2tf32(acc.x * r);
                dptr[1] = f2tf32(acc.y * r);
                dptr[2] = f2tf32(acc.z * r);
                dptr[3] = f2tf32(acc.w * r);
            }
        }
    }
    __syncthreads();

    // ---- Phase 2: wmma ----
    const int warp = tid >> 5;
    const int nt   = warp & 7;       // node tile (16 rows)
    const int ch   = warp >> 3;      // col half

    wmma::fragment<wmma::accumulator, 16, 16, 8, float> fc[JT];
#pragma unroll
    for (int j = 0; j < JT; j++) wmma::fill_fragment(fc[j], 0.0f);

#pragma unroll
    for (int k8 = 0; k8 < K / 8; k8++) {
        wmma::fragment<wmma::matrix_a, 16, 16, 8, wmma::precision::tf32, wmma::row_major> fa;
        wmma::load_matrix_sync(fa, &Is[nt * 16 * LDI + k8 * 8], LDI);
#pragma unroll
        for (int j = 0; j < JT; j++) {
            wmma::fragment<wmma::matrix_b, 16, 16, 8, wmma::precision::tf32, wmma::row_major> fb;
            wmma::load_matrix_sync(fb, &Wt[k8 * 8 * COUT + (ch * JT + j) * 16], COUT);
            wmma::mma_sync(fc[j], fa, fb, fc[j]);
        }
    }
    __syncthreads();   // all warps done reading Is

    // Stash accumulators into Is (reused as [BN][LDI] output staging)
#pragma unroll
    for (int j = 0; j < JT; j++)
        wmma::store_matrix_sync(&Is[nt * 16 * LDI + (ch * JT + j) * 16],
                                fc[j], LDI, wmma::mem_row_major);
    __syncthreads();

    // Epilogue: bias + activation + coalesced store
    for (int i = tid; i < BN * COUT / 4; i += 512) {
        int n = i / (COUT / 4), q = i % (COUT / 4);
        float4 v = *reinterpret_cast<float4*>(&Is[n * LDI + q * 4]);
        float4 b4 = *reinterpret_cast<const float4*>(&Bs[q * 4]);
        float4 o;
        o.x = actf<ACT>(v.x + b4.x);
        o.y = actf<ACT>(v.y + b4.y);
        o.z = actf<ACT>(v.z + b4.z);
        o.w = actf<ACT>(v.w + b4.w);
        reinterpret_cast<float4*>(out)[(size_t)(base + n) * (COUT / 4) + q] = o;
    }
}

// ---------------------------------------------------------------------------
// Launch
// ---------------------------------------------------------------------------
static inline int smem_bytes(int K, int COUT) {
    return (K * COUT + COUT + 64 * (K + 1)) * (int)sizeof(float);
}
static inline int wmma_smem_bytes(int K, int COUT) {
    return (128 * (K + 4) + COUT) * (int)sizeof(float);
}

extern "C" void kernel_launch(void* const* d_in, const int* in_sizes, int n_in,
                              void* d_out, int out_size) {
    const float* x     = (const float*)d_in[0];
    const int*   ei    = (const int*)d_in[1];      // [2, E]
    const float* W_lin = (const float*)d_in[3];
    const float* b_lin = (const float*)d_in[4];
    const float* Ws3   = (const float*)d_in[5];
    const float* Wn3   = (const float*)d_in[6];
    const float* b3    = (const float*)d_in[7];
    const float* Ws2   = (const float*)d_in[8];
    const float* Wn2   = (const float*)d_in[9];
    const float* b2    = (const float*)d_in[10];
    const float* Ws1   = (const float*)d_in[11];
    const float* Wn1   = (const float*)d_in[12];
    const float* b1    = (const float*)d_in[13];
    float* out = (float*)d_out;

    const int* src = ei;
    const int* dst = ei + NE;

    float *h0, *h1, *h2, *agg, *rdeg, *W1t, *W2t;
    int *deg, *rowoff, *cursor, *col, *bsum;
    cudaGetSymbolAddress((void**)&h0,     g_h0);
    cudaGetSymbolAddress((void**)&h1,     g_h1);
    cudaGetSymbolAddress((void**)&h2,     g_h2);
    cudaGetSymbolAddress((void**)&agg,    g_agg);
    cudaGetSymbolAddress((void**)&rdeg,   g_rdeg);
    cudaGetSymbolAddress((void**)&W1t,    g_W1t);
    cudaGetSymbolAddress((void**)&W2t,    g_W2t);
    cudaGetSymbolAddress((void**)&deg,    g_deg);
    cudaGetSymbolAddress((void**)&rowoff, g_rowoff);
    cudaGetSymbolAddress((void**)&cursor, g_cursor);
    cudaGetSymbolAddress((void**)&col,    g_col);
    cudaGetSymbolAddress((void**)&bsum,   g_bsum);

    const int wsmem_L1 = wmma_smem_bytes(128, 128);   // ~66.5KB -> 2 CTA/SM
    const int wsmem_L2 = wmma_smem_bytes(64, 64);     // ~34.3KB -> 4 CTA/SM
    cudaFuncSetAttribute((const void*)wmma_fused_kernel<64, 128, 2>,
                         cudaFuncAttributeMaxDynamicSharedMemorySize, wsmem_L1 + 1024);
    cudaFuncSetAttribute((const void*)wmma_fused_kernel<32, 64, 1>,
                         cudaFuncAttributeMaxDynamicSharedMemorySize, wsmem_L2 + 1024);

    const int T  = 256;
    const int NB = NN / 64;          // SIMT combine grid
    const int WB = NN / 128;         // wmma grid
    const int GW = NN * 32 / T;      // gather grid (1 warp/node)

    // ---- CSR build + weight prep ----
    zero2_int<<<NN / T, T>>>(deg, cursor);
    deg_kernel<<<NE / T, T>>>(dst, deg);
    scanA<<<512, 256>>>(deg, rowoff, bsum, rdeg);
    scanB<<<1, 512>>>(bsum);
    scanC<<<512, 256>>>(rowoff, bsum);
    fill_kernel<<<NE / T, T>>>(src, dst, rowoff, cursor, col);
    prep_w<<<64, 256>>>(Ws1, Wn1, Ws2, Wn2);

    // ---- Linear(16,16) ----
    combine_kernel<16, 16, false, 0><<<NB, T, smem_bytes(16, 16)>>>(
        x, nullptr, W_lin, nullptr, b_lin, h0);

    // ---- Block3: 16 -> 32, relu (gather + SIMT combine) ----
    gather_kernel<4><<<GW, T>>>(rowoff, deg, col, rdeg, h0, agg);
    combine_kernel<16, 32, true, 1><<<NB, T, smem_bytes(32, 32)>>>(
        h0, agg, Ws3, Wn3, b3, h1);

    // ---- Block2: 32 -> 64, relu (fused gather + wmma tf32) ----
    wmma_fused_kernel<32, 64, 1><<<WB, 512, wsmem_L2>>>(
        h1, rowoff, deg, col, rdeg, W2t, b2, h2);

    // ---- Block1: 64 -> 128, sigmoid -> d_out (fused gather + wmma tf32) ----
    wmma_fused_kernel<64, 128, 2><<<WB, 512, wsmem_L1>>>(
        h2, rowoff, deg, col, rdeg, W1t, b1, out);
}